// round 6
// baseline (speedup 1.0000x reference)
#include <cuda_runtime.h>

// TemporalScaledDotProductforCrossAttention — GB300 fused kernel.
// One CTA per (b,h,n) site; 4 warps = 4 attention variants.
// Lane layout: lane = 2*q + h, q in [0,12) score row, h = D-half (32 floats).
// FIX R6: mask staging now covers all 144 entries (blockDim=128 < 144 left
// smask[128..143] uninitialized -> q=10/11 rows used garbage mask).
// Bank-conflict-free B/V loads via column rotation j = (i + 4h) & 7.

static constexpr int STR4  = 17;          // padded float4 stride per 12-row tile
static constexpr int TILE4 = 12 * STR4;   // 204 float4 per tile

__device__ __forceinline__ float dot4(float4 a, float4 b, float acc) {
    acc = fmaf(a.x, b.x, acc);
    acc = fmaf(a.y, b.y, acc);
    acc = fmaf(a.z, b.z, acc);
    acc = fmaf(a.w, b.w, acc);
    return acc;
}

__global__ __launch_bounds__(128)
void tsdp_kernel(const float* __restrict__ Qf, const float* __restrict__ Kf,
                 const float* __restrict__ Vf, const float* __restrict__ Qs,
                 const float* __restrict__ Ks, const float* __restrict__ Vs,
                 const float* __restrict__ Kj, const float* __restrict__ Vfp,
                 const int* __restrict__ mask, float* __restrict__ out,
                 int nsite)
{
    // tiles: 0=Qf 1=Kf 2=Vf 3=Qs 4=Ks 5=Vs 6=Qfs(flow-speed)
    __shared__ float4 tiles[7][TILE4];
    __shared__ int smask[144];

    const int site = blockIdx.x;
    const int tid  = threadIdx.x;

    // ---- Stage: gmem -> smem (coalesced float4), fuse flow-speed transform ----
    {
        const long long base = (long long)site * 192;
        const float4* gQf = (const float4*)Qf + base;
        const float4* gKf = (const float4*)Kf + base;
        const float4* gVf = (const float4*)Vf + base;
        const float4* gQs = (const float4*)Qs + base;
        const float4* gKs = (const float4*)Ks + base;
        const float4* gVs = (const float4*)Vs + base;

        #pragma unroll
        for (int rep = 0; rep < 2; rep++) {
            int f = tid + rep * 128;
            if (f < 192) {
                int r = f >> 4, c = f & 15;
                int idx = r * STR4 + c;
                tiles[0][idx] = gQf[f];
                tiles[1][idx] = gKf[f];
                tiles[2][idx] = gVf[f];
                float4 v = gQs[f];
                tiles[3][idx] = v;
                tiles[4][idx] = gKs[f];
                tiles[5][idx] = gVs[f];
                // Qfs[k][d] = Kj[k] * (x - x*x / (Vfp[k] + 1e-5))
                float kj    = __ldg(Kj + r);
                float denom = __ldg(Vfp + r) + 1e-5f;
                float4 w;
                w.x = kj * (v.x - (v.x * v.x) / denom);
                w.y = kj * (v.y - (v.y * v.y) / denom);
                w.z = kj * (v.z - (v.z * v.z) / denom);
                w.w = kj * (v.w - (v.w * v.w) / denom);
                tiles[6][idx] = w;
            }
        }
    }
    // FIX: cover ALL 144 mask entries with 128 threads (strided)
    for (int i = tid; i < 144; i += 128) smask[i] = mask[i];
    __syncthreads();

    const int w    = tid >> 5;
    const int lane = tid & 31;
    if (lane >= 24) return;                 // no further block syncs

    // per-warp operand selection: A (rows q), B (rows k), V
    int aI, bI, vI;
    if      (w == 0) { aI = 0; bI = 1; vI = 2; }  // ff: Qf·Kf^T  -> Vf
    else if (w == 1) { aI = 1; bI = 6; vI = 2; }  // fs: Kf·Qfs^T -> Vf
    else if (w == 2) { aI = 4; bI = 0; vI = 5; }  // sf: Ks·Qf^T  -> Vs
    else             { aI = 3; bI = 4; vI = 5; }  // ss: Qs·Ks^T  -> Vs

    const float4* A4 = tiles[aI];
    const float4* B4 = tiles[bI];
    const float4* V4 = tiles[vI];

    const int q   = lane >> 1;   // score row owned by this lane
    const int h   = lane & 1;    // D-half owned by this lane
    const int rot = 4 * h;       // bank-conflict-avoidance rotation

    // ---- Scores: S[q][k] = dot(A[q], B[k]) over D=64, split across h ----
    float s[12];
    #pragma unroll
    for (int k = 0; k < 12; k++) s[k] = 0.0f;

    #pragma unroll
    for (int ch = 0; ch < 2; ch++) {
        float4 a[4];
        int jj[4];
        #pragma unroll
        for (int i = 0; i < 4; i++) {
            jj[i] = ((ch * 4 + i + rot) & 7);
            a[i]  = A4[q * STR4 + h * 8 + jj[i]];
        }
        #pragma unroll
        for (int k = 0; k < 12; k++) {
            float acc = 0.0f;
            #pragma unroll
            for (int i = 0; i < 4; i++) {
                float4 b = B4[k * STR4 + h * 8 + jj[i]];  // conflict-free pair
                acc = dot4(a[i], b, acc);
            }
            s[k] += acc;
        }
    }

    // cross-half reduce + scale + exact mask select
    #pragma unroll
    for (int k = 0; k < 12; k++) {
        float v = s[k] + __shfl_xor_sync(0x00ffffffu, s[k], 1);
        s[k] = (smask[q * 12 + k] == 1) ? -1e9f : v * 0.125f;
    }

    // ---- Softmax over k (both h-lanes redundantly; avoids a broadcast) ----
    float mx = s[0];
    #pragma unroll
    for (int k = 1; k < 12; k++) mx = fmaxf(mx, s[k]);
    float sum = 0.0f;
    #pragma unroll
    for (int k = 0; k < 12; k++) { s[k] = __expf(s[k] - mx); sum += s[k]; }
    const float rs = 1.0f / sum;

    // ---- Output: C[q][d] = sum_k z[q][k] * V[k][d]; lane covers 32 d's ----
    float4 c[8];
    #pragma unroll
    for (int i = 0; i < 8; i++) c[i] = make_float4(0.f, 0.f, 0.f, 0.f);

    #pragma unroll
    for (int k = 0; k < 12; k++) {
        float zk = s[k] * rs;
        #pragma unroll
        for (int i = 0; i < 8; i++) {
            int j    = (i + rot) & 7;
            float4 v = V4[k * STR4 + h * 8 + j];          // conflict-free pair
            c[i].x = fmaf(zk, v.x, c[i].x);
            c[i].y = fmaf(zk, v.y, c[i].y);
            c[i].z = fmaf(zk, v.z, c[i].z);
            c[i].w = fmaf(zk, v.w, c[i].w);
        }
    }

    // outputs concatenated in order (c_ff, c_fs, c_sf, c_ss)
    float4* o = (float4*)out + ((long long)w * nsite + site) * 192 + q * 16 + h * 8;
    #pragma unroll
    for (int i = 0; i < 8; i++) {
        int j = (i + rot) & 7;
        o[j] = c[i];
    }
}

extern "C" void kernel_launch(void* const* d_in, const int* in_sizes, int n_in,
                              void* d_out, int out_size) {
    const int nsite = in_sizes[0] / 768;   // B*H*L1 = 39296
    tsdp_kernel<<<nsite, 128>>>(
        (const float*)d_in[0], (const float*)d_in[1], (const float*)d_in[2],
        (const float*)d_in[3], (const float*)d_in[4], (const float*)d_in[5],
        (const float*)d_in[6], (const float*)d_in[7],
        (const int*)d_in[8],
        (float*)d_out, nsite);
}